// round 6
// baseline (speedup 1.0000x reference)
#include <cuda_runtime.h>
#include <cuda_bf16.h>

// ---------------------------------------------------------------------------
// Problem constants
// ---------------------------------------------------------------------------
#define H_  1024
#define G_  4096      // 4*H
#define B_  64
#define T_  256
#define M_  16384     // B*T

// ---------------------------------------------------------------------------
// Scratch (device globals — no allocation allowed)
// ---------------------------------------------------------------------------
__device__ float g_xg[(size_t)M_ * G_];        // 256 MB: per-layer input projections
__device__ float g_hseqA[(size_t)M_ * H_];     // 64 MB : layer output sequence (t-major rows)
__device__ float g_hseqB[(size_t)M_ * H_];     // 64 MB : ping-pong
__device__ float g_hbuf[2][H_ * B_];           // h state, [unit][batch] layout, double buffered
__device__ unsigned g_bar_count;
__device__ volatile unsigned g_bar_gen;

typedef unsigned long long u64;

// ---------------------------------------------------------------------------
// Packed f32x2 helpers (B300: FFMA rt=2/SMSP; f32x2 doubles fp32 throughput)
// ---------------------------------------------------------------------------
__device__ __forceinline__ u64 pack2(float x, float y) {
    u64 r; asm("mov.b64 %0, {%1, %2};" : "=l"(r) : "f"(x), "f"(y)); return r;
}
__device__ __forceinline__ void unpack2(u64 v, float& x, float& y) {
    asm("mov.b64 {%0, %1}, %2;" : "=f"(x), "=f"(y) : "l"(v));
}
__device__ __forceinline__ void ffma2(u64& acc, u64 a, u64 b) {
    asm("fma.rn.f32x2 %0, %1, %2, %3;" : "=l"(acc) : "l"(a), "l"(b), "l"(acc));
}
__device__ __forceinline__ float sigmf(float x) { return 1.0f / (1.0f + expf(-x)); }

// ---------------------------------------------------------------------------
// Grid barrier (sense-reversing; 128 co-resident CTAs).
// __threadfence() is gpu-scope => CCTL.IVALL on sm_103a (flushes L1D), so
// cross-SM h-state visibility is guaranteed on both sides of the barrier.
// ---------------------------------------------------------------------------
__device__ __forceinline__ void grid_barrier(unsigned nblocks) {
    __syncthreads();
    if (threadIdx.x == 0) {
        unsigned gen = g_bar_gen;
        __threadfence();
        unsigned t = atomicAdd(&g_bar_count, 1u);
        if (t == nblocks - 1u) {
            g_bar_count = 0u;
            __threadfence();
            g_bar_gen = gen + 1u;
        } else {
            while (g_bar_gen == gen) { }
        }
        __threadfence();
    }
    __syncthreads();
}

// ---------------------------------------------------------------------------
// Input-projection GEMM: xg[m, n] = sum_k A[m,k] * W[n,k] + bih[n] + bhh[n]
//   A rows are m = t*64 + b (t-major). For layer 0 (remap=1) the input row in
//   x is b*256 + t (x reshaped [B,T,256] is b-major).
//   BM=128, BN=64, BK=16, 256 threads, 8x4 microtile, f32x2 FMAs.
// ---------------------------------------------------------------------------
#define GBM 128
#define GBN 64
#define GBK 16

__global__ __launch_bounds__(256) void gemm_xg_kernel(
    const float* __restrict__ Aext, int insel,
    const float* __restrict__ W,
    const float* __restrict__ bih, const float* __restrict__ bhh,
    int K, int remap)
{
    __shared__ __align__(16) float sA[GBK][GBM];   // [k][m]
    __shared__ __align__(16) float sB[GBK][GBN];   // [k][n]

    const float* A = Aext ? Aext : (insel == 1 ? g_hseqA : g_hseqB);
    const int tid = threadIdx.x;
    const int bn = blockIdx.x * GBN;   // N fastest -> consecutive blocks share A (L2)
    const int bm = blockIdx.y * GBM;
    const int tm = (tid >> 4) * 8;     // 8 rows per thread
    const int tn = (tid & 15) * 4;     // 4 cols per thread

    u64 acc[4][4];                     // row-pairs x cols, packed over row pairs
    #pragma unroll
    for (int p = 0; p < 4; p++)
        #pragma unroll
        for (int j = 0; j < 4; j++) acc[p][j] = 0ull;

    // A loader: 128 rows x 16 cols = 512 float4; thread -> 2 consecutive float4
    const int a_row = tid >> 1;
    const int a_kq  = (tid & 1) * 2;
    int grow = bm + a_row;
    if (remap) grow = (grow & 63) * 256 + (grow >> 6);   // (b, t) -> x row b*256+t
    const float4* Arow = (const float4*)(A + (size_t)grow * K);
    // W loader: 64 rows x 16 cols = 256 float4; one per thread
    const int b_row = tid >> 2;
    const int b_kq  = tid & 3;
    const float4* Wrow = (const float4*)(W + (size_t)(bn + b_row) * K);

    for (int k0 = 0; k0 < K; k0 += GBK) {
        float4 av0 = Arow[(k0 >> 2) + a_kq];
        float4 av1 = Arow[(k0 >> 2) + a_kq + 1];
        float4 bv  = Wrow[(k0 >> 2) + b_kq];
        __syncthreads();
        sA[a_kq*4 + 0][a_row] = av0.x;
        sA[a_kq*4 + 1][a_row] = av0.y;
        sA[a_kq*4 + 2][a_row] = av0.z;
        sA[a_kq*4 + 3][a_row] = av0.w;
        sA[a_kq*4 + 4][a_row] = av1.x;
        sA[a_kq*4 + 5][a_row] = av1.y;
        sA[a_kq*4 + 6][a_row] = av1.z;
        sA[a_kq*4 + 7][a_row] = av1.w;
        sB[b_kq*4 + 0][b_row] = bv.x;
        sB[b_kq*4 + 1][b_row] = bv.y;
        sB[b_kq*4 + 2][b_row] = bv.z;
        sB[b_kq*4 + 3][b_row] = bv.w;
        __syncthreads();
        #pragma unroll
        for (int k = 0; k < GBK; k++) {
            ulonglong2 aA = *(const ulonglong2*)&sA[k][tm];     // (m0,m1),(m2,m3)
            ulonglong2 aB = *(const ulonglong2*)&sA[k][tm + 4]; // (m4,m5),(m6,m7)
            float4 bq = *(const float4*)&sB[k][tn];
            u64 ap[4] = { aA.x, aA.y, aB.x, aB.y };
            u64 bp[4] = { pack2(bq.x, bq.x), pack2(bq.y, bq.y),
                          pack2(bq.z, bq.z), pack2(bq.w, bq.w) };
            #pragma unroll
            for (int p = 0; p < 4; p++)
                #pragma unroll
                for (int j = 0; j < 4; j++)
                    ffma2(acc[p][j], ap[p], bp[j]);
        }
    }

    float bb[4];
    #pragma unroll
    for (int j = 0; j < 4; j++) bb[j] = bih[bn + tn + j] + bhh[bn + tn + j];
    #pragma unroll
    for (int p = 0; p < 4; p++) {
        float r0[4], r1[4];
        #pragma unroll
        for (int j = 0; j < 4; j++) unpack2(acc[p][j], r0[j], r1[j]);
        float* o0 = g_xg + (size_t)(bm + tm + 2*p) * G_ + bn + tn;
        float* o1 = o0 + G_;
        *(float4*)o0 = make_float4(r0[0]+bb[0], r0[1]+bb[1], r0[2]+bb[2], r0[3]+bb[3]);
        *(float4*)o1 = make_float4(r1[0]+bb[0], r1[1]+bb[1], r1[2]+bb[2], r1[3]+bb[3]);
    }
}

// ---------------------------------------------------------------------------
// Persistent recurrent kernel: one launch runs all T=256 steps of one layer.
// 128 CTAs x 256 threads. CTA bid owns hidden units [bid*8, bid*8+8) for all
// 4 gates: 32 w_hh rows (32x1024 fp32 = 128 KB) resident in SMEM for the
// whole layer. h state in g_hbuf[par][unit*64 + batch], double buffered,
// one grid barrier per step.
// Thread (b = tid&63, rg = tid>>6) accumulates gate rg for 8 units, batch b.
// ---------------------------------------------------------------------------
#define RBLK 128
#define REC_SMEM_FLOATS (32*1024 + 512 + 2048 + 512)

__global__ __launch_bounds__(256, 1) void lstm_rec_kernel(
    const float* __restrict__ whh, int osel)
{
    extern __shared__ __align__(16) float smem[];
    float* sW = smem;               // [32][1024]  w_hh slice (row = gate*8 + unit)
    float* sC = sW + 32*1024;       // [512]  c state, cell = unit*64 + batch
    float* sG = sC + 512;           // [32][64] gate pre-activations
    float* sH = sG + 2048;          // [512]  h staging for hseq transpose-store

    const int tid = threadIdx.x;
    const int bid = blockIdx.x;
    const int u0  = bid * 8;
    const int b   = tid & 63;
    const int rg  = tid >> 6;
    float* hseq = (osel == 1) ? g_hseqA : g_hseqB;

    // Load w_hh slice: rows q*H + u0 + j  ->  sW row q*8+j
    #pragma unroll
    for (int i = 0; i < 32; i++) {
        int f  = tid + i * 256;        // float4 index in [0, 8192)
        int r  = f >> 8;               // sW row (256 float4 per row)
        int kq = f & 255;
        int q = r >> 3, j = r & 7;
        ((float4*)sW)[r * 256 + kq] =
            *(const float4*)(whh + (size_t)(q * H_ + u0 + j) * H_ + kq * 4);
    }
    sC[tid] = 0.f; sC[tid + 256] = 0.f;
    // zero own slice of h0 (contiguous 512 floats at u0*64)
    g_hbuf[0][u0 * 64 + tid] = 0.f;
    g_hbuf[0][u0 * 64 + tid + 256] = 0.f;
    __syncthreads();
    grid_barrier(gridDim.x);

    int par = 0;
    const float* wr = sW + (rg * 8) * 1024;
    for (int t = 0; t < T_; t++) {
        // init accumulators from xg (row m = t*64+b, cols rg*H + u0 .. +7)
        const float4* xr = (const float4*)(g_xg + (size_t)(t * 64 + b) * G_ + rg * H_ + u0);
        float4 x0 = xr[0], x1 = xr[1];
        u64 acc[8];
        acc[0] = pack2(x0.x, 0.f); acc[1] = pack2(x0.y, 0.f);
        acc[2] = pack2(x0.z, 0.f); acc[3] = pack2(x0.w, 0.f);
        acc[4] = pack2(x1.x, 0.f); acc[5] = pack2(x1.y, 0.f);
        acc[6] = pack2(x1.z, 0.f); acc[7] = pack2(x1.w, 0.f);

        const float* hb = g_hbuf[par] + b;       // h(k) at hb[k*64]
        #pragma unroll 2
        for (int k = 0; k < H_; k += 4) {
            float h0 = __ldcg(hb + (k + 0) * 64);
            float h1 = __ldcg(hb + (k + 1) * 64);
            float h2 = __ldcg(hb + (k + 2) * 64);
            float h3 = __ldcg(hb + (k + 3) * 64);
            u64 hp01 = pack2(h0, h1);
            u64 hp23 = pack2(h2, h3);
            #pragma unroll
            for (int j = 0; j < 8; j++) {
                ulonglong2 wv = *(const ulonglong2*)(wr + j * 1024 + k);
                ffma2(acc[j], hp01, wv.x);     // even/odd-k partial sums
                ffma2(acc[j], hp23, wv.y);
            }
        }
        #pragma unroll
        for (int j = 0; j < 8; j++) {
            float lo, hi; unpack2(acc[j], lo, hi);
            sG[(rg * 8 + j) * 64 + b] = lo + hi;
        }
        __syncthreads();

        // pointwise LSTM cell update: 512 cells over 256 threads
        #pragma unroll
        for (int rep = 0; rep < 2; rep++) {
            int cell = tid + rep * 256;
            int j = cell >> 6, bb = cell & 63;
            float vi = sG[(0 * 8 + j) * 64 + bb];
            float vf = sG[(1 * 8 + j) * 64 + bb];
            float vg = sG[(2 * 8 + j) * 64 + bb];
            float vo = sG[(3 * 8 + j) * 64 + bb];
            float c = sigmf(vf) * sC[cell] + sigmf(vi) * tanhf(vg);
            sC[cell] = c;
            float hv = sigmf(vo) * tanhf(c);
            g_hbuf[par ^ 1][u0 * 64 + cell] = hv;   // coalesced [unit][batch]
            sH[cell] = hv;
        }
        __syncthreads();

        // hseq store, j-contiguous: row m = t*64+b, cols u0..u0+7
        #pragma unroll
        for (int rep = 0; rep < 2; rep++) {
            int idx = tid + rep * 256;
            int j2 = idx & 7, b3 = idx >> 3;
            hseq[(size_t)(t * 64 + b3) * H_ + u0 + j2] = sH[j2 * 64 + b3];
        }
        grid_barrier(gridDim.x);
        par ^= 1;
    }
}

// ---------------------------------------------------------------------------
// Final FC: out[b] = dot(h_T[b,:], fc_w) + fc_b
// ---------------------------------------------------------------------------
__global__ void fc_kernel(const float* __restrict__ fcw, const float* __restrict__ fcb,
                          float* __restrict__ out)
{
    int bb = blockIdx.x, tid = threadIdx.x;
    const float* h = g_hseqA + (size_t)(255 * 64 + bb) * H_;
    float s = 0.f;
    for (int k = tid * 4; k < H_; k += 128 * 4) {
        float4 hv = *(const float4*)(h + k);
        float4 wv = *(const float4*)(fcw + k);
        s += hv.x * wv.x + hv.y * wv.y + hv.z * wv.z + hv.w * wv.w;
    }
    #pragma unroll
    for (int o = 16; o; o >>= 1) s += __shfl_xor_sync(0xffffffffu, s, o);
    __shared__ float ws[4];
    if ((tid & 31) == 0) ws[tid >> 5] = s;
    __syncthreads();
    if (tid == 0) out[bb] = ws[0] + ws[1] + ws[2] + ws[3] + fcb[0];
}

// ---------------------------------------------------------------------------
// Launch
// ---------------------------------------------------------------------------
extern "C" void kernel_launch(void* const* d_in, const int* in_sizes, int n_in,
                              void* d_out, int out_size)
{
    const float* x     = (const float*)d_in[0];
    const float* w_ih0 = (const float*)d_in[1];
    const float* w_hh0 = (const float*)d_in[2];
    const float* b_ih0 = (const float*)d_in[3];
    const float* b_hh0 = (const float*)d_in[4];
    const float* w_ih1 = (const float*)d_in[5];
    const float* w_hh1 = (const float*)d_in[6];
    const float* b_ih1 = (const float*)d_in[7];
    const float* b_hh1 = (const float*)d_in[8];
    const float* w_ih2 = (const float*)d_in[9];
    const float* w_hh2 = (const float*)d_in[10];
    const float* b_ih2 = (const float*)d_in[11];
    const float* b_hh2 = (const float*)d_in[12];
    const float* fc_w  = (const float*)d_in[13];
    const float* fc_b  = (const float*)d_in[14];
    float* out = (float*)d_out;

    size_t rec_smem = (size_t)REC_SMEM_FLOATS * sizeof(float);   // 143,360 B
    cudaFuncSetAttribute(lstm_rec_kernel,
                         cudaFuncAttributeMaxDynamicSharedMemorySize, (int)rec_smem);

    dim3 ggrid(G_ / GBN, M_ / GBM);   // (64, 128)

    // layer 0: input is x (b-major rows -> remap), K=256
    gemm_xg_kernel<<<ggrid, 256>>>(x, 0, w_ih0, b_ih0, b_hh0, 256, 1);
    lstm_rec_kernel<<<RBLK, 256, rec_smem>>>(w_hh0, 1);   // -> hseqA
    // layer 1: input hseqA, K=1024
    gemm_xg_kernel<<<ggrid, 256>>>(nullptr, 1, w_ih1, b_ih1, b_hh1, H_, 0);
    lstm_rec_kernel<<<RBLK, 256, rec_smem>>>(w_hh1, 2);   // -> hseqB
    // layer 2: input hseqB, K=1024
    gemm_xg_kernel<<<ggrid, 256>>>(nullptr, 2, w_ih2, b_ih2, b_hh2, H_, 0);
    lstm_rec_kernel<<<RBLK, 256, rec_smem>>>(w_hh2, 1);   // -> hseqA
    // final FC
    fc_kernel<<<B_, 128>>>(fc_w, fc_b, out);
}

// round 10
// speedup vs baseline: 1.0479x; 1.0479x over previous
#include <cuda_runtime.h>
#include <cuda_bf16.h>
#include <cstdint>

// ---------------------------------------------------------------------------
// Problem constants
// ---------------------------------------------------------------------------
#define H_  1024
#define G_  4096      // 4*H
#define B_  64
#define T_  256
#define M_  16384     // B*T

// ---------------------------------------------------------------------------
// Scratch (device globals — no allocation allowed)
// ---------------------------------------------------------------------------
__device__ float g_xg[(size_t)M_ * G_];        // 256 MB: per-layer input projections
__device__ float g_hseqA[(size_t)M_ * H_];     // 64 MB : layer output sequence (t-major rows)
__device__ float g_hseqB[(size_t)M_ * H_];     // 64 MB : ping-pong
__device__ float g_hbuf[2][H_ * B_];           // h state, [unit][batch] layout, double buffered
__device__ unsigned g_bar_count;
__device__ volatile unsigned g_bar_gen;

typedef unsigned long long u64;

// ---------------------------------------------------------------------------
// Packed f32x2 helpers (recurrent kernel)
// ---------------------------------------------------------------------------
__device__ __forceinline__ u64 pack2(float x, float y) {
    u64 r; asm("mov.b64 %0, {%1, %2};" : "=l"(r) : "f"(x), "f"(y)); return r;
}
__device__ __forceinline__ void unpack2(u64 v, float& x, float& y) {
    asm("mov.b64 {%0, %1}, %2;" : "=f"(x), "=f"(y) : "l"(v));
}
__device__ __forceinline__ void ffma2(u64& acc, u64 a, u64 b) {
    asm("fma.rn.f32x2 %0, %1, %2, %3;" : "=l"(acc) : "l"(a), "l"(b), "l"(acc));
}
__device__ __forceinline__ float sigmf(float x) { return 1.0f / (1.0f + expf(-x)); }

// ---------------------------------------------------------------------------
// Grid barrier (sense-reversing; 128 co-resident CTAs)
// ---------------------------------------------------------------------------
__device__ __forceinline__ void grid_barrier(unsigned nblocks) {
    __syncthreads();
    if (threadIdx.x == 0) {
        unsigned gen = g_bar_gen;
        __threadfence();
        unsigned t = atomicAdd(&g_bar_count, 1u);
        if (t == nblocks - 1u) {
            g_bar_count = 0u;
            __threadfence();
            g_bar_gen = gen + 1u;
        } else {
            while (g_bar_gen == gen) { }
        }
        __threadfence();
    }
    __syncthreads();
}

// ---------------------------------------------------------------------------
// bf16 split helpers (GEMM): x = hi(x) + lo(x), each bf16 (8-bit mantissa)
// ---------------------------------------------------------------------------
__device__ __forceinline__ void split8(const float4 a, const float4 b,
                                       uint4& h, uint4& l)
{
    float v[8] = {a.x, a.y, a.z, a.w, b.x, b.y, b.z, b.w};
    unsigned short hs[8], ls[8];
    #pragma unroll
    for (int q = 0; q < 8; q++) {
        __nv_bfloat16 bh = __float2bfloat16(v[q]);
        hs[q] = __bfloat16_as_ushort(bh);
        float res = v[q] - __bfloat162float(bh);
        ls[q] = __bfloat16_as_ushort(__float2bfloat16(res));
    }
    h.x = (uint32_t)hs[0] | ((uint32_t)hs[1] << 16);
    h.y = (uint32_t)hs[2] | ((uint32_t)hs[3] << 16);
    h.z = (uint32_t)hs[4] | ((uint32_t)hs[5] << 16);
    h.w = (uint32_t)hs[6] | ((uint32_t)hs[7] << 16);
    l.x = (uint32_t)ls[0] | ((uint32_t)ls[1] << 16);
    l.y = (uint32_t)ls[2] | ((uint32_t)ls[3] << 16);
    l.z = (uint32_t)ls[4] | ((uint32_t)ls[5] << 16);
    l.w = (uint32_t)ls[6] | ((uint32_t)ls[7] << 16);
}

__device__ __forceinline__ void ldsm_x4(uint32_t* r, uint32_t addr) {
    asm volatile("ldmatrix.sync.aligned.m8n8.x4.shared.b16 {%0,%1,%2,%3}, [%4];"
        : "=r"(r[0]), "=r"(r[1]), "=r"(r[2]), "=r"(r[3]) : "r"(addr));
}
__device__ __forceinline__ void mma_bf16(float* c, const uint32_t* a, const uint32_t* b) {
    asm volatile(
        "mma.sync.aligned.m16n8k16.row.col.f32.bf16.bf16.f32 "
        "{%0,%1,%2,%3},{%4,%5,%6,%7},{%8,%9},{%0,%1,%2,%3};"
        : "+f"(c[0]), "+f"(c[1]), "+f"(c[2]), "+f"(c[3])
        : "r"(a[0]), "r"(a[1]), "r"(a[2]), "r"(a[3]), "r"(b[0]), "r"(b[1]));
}

// ---------------------------------------------------------------------------
// Tensor-core input-projection GEMM (bf16x3 split, rel err ~1e-5):
//   xg[m, n] = sum_k A[m,k] * W[n,k] + bih[n] + bhh[n]
// BM=128, BN=128, BK=32, 256 threads (8 warps, warp tile 64x32),
// double-buffered SMEM, XOR-swizzled 16B units.
// B tile is stored [n][k] (k contiguous) => B fragments come from
// NON-transposed ldmatrix (lane gets n=lane/4, two consecutive k) — this is
// the m16n8k16 row.col B layout. (.trans here was the R6 correctness bug.)
// For layer 0 (remap=1), A row (t*64+b) lives at x row (b*256+t).
// ---------------------------------------------------------------------------
#define STAGE_BYTES 32768    // Ah(8K) Al(8K) Bh(8K) Bl(8K)

__global__ __launch_bounds__(256, 1) void gemm_mma_kernel(
    const float* __restrict__ Aext, int insel,
    const float* __restrict__ W,
    const float* __restrict__ bih, const float* __restrict__ bhh,
    int K, int remap)
{
    extern __shared__ __align__(16) char smem_raw[];
    const float* A = Aext ? Aext : (insel == 1 ? g_hseqA : g_hseqB);

    const int tid  = threadIdx.x;
    const int lane = tid & 31;
    const int wid  = tid >> 5;
    const int bn = blockIdx.x * 128;
    const int bm = blockIdx.y * 128;
    const int mw = (wid & 1) * 64;     // warp m offset in block
    const int nw = (wid >> 1) * 32;    // warp n offset in block

    // ---- loader indexing: thread t owns row lr, 16B-units lku, lku+1 ----
    const int lr  = tid >> 1;          // 0..127
    const int lku = (tid & 1) * 2;     // 0 or 2
    int arow = bm + lr;
    if (remap) arow = (arow & 63) * 256 + (arow >> 6);
    const float4* Ag = (const float4*)(A + (size_t)arow * K);
    const float4* Wg = (const float4*)(W + (size_t)(bn + lr) * K);

    const uint32_t s_base = (uint32_t)__cvta_generic_to_shared(smem_raw);
    // per-thread swizzled store offsets (bytes within a tile)
    const int ph0 = (lku ^ (lr & 3));
    const int ph1 = ((lku + 1) ^ (lr & 3));
    const int soff0 = lr * 64 + ph0 * 16;
    const int soff1 = lr * 64 + ph1 * 16;

    float acc[4][4][4];
    #pragma unroll
    for (int i = 0; i < 4; i++)
        #pragma unroll
        for (int j = 0; j < 4; j++)
            #pragma unroll
            for (int q = 0; q < 4; q++) acc[i][j][q] = 0.f;

    float4 ra[4], rb[4];
    const int KS = K / 32;

    // prologue: load + store stage 0
    {
        ra[0] = Ag[lku * 2];     ra[1] = Ag[lku * 2 + 1];
        ra[2] = Ag[lku * 2 + 2]; ra[3] = Ag[lku * 2 + 3];
        rb[0] = Wg[lku * 2];     rb[1] = Wg[lku * 2 + 1];
        rb[2] = Wg[lku * 2 + 2]; rb[3] = Wg[lku * 2 + 3];
        uint4 h4, l4;
        char* sb = smem_raw;
        split8(ra[0], ra[1], h4, l4);
        *(uint4*)(sb + soff0) = h4;           *(uint4*)(sb + 8192 + soff0) = l4;
        split8(ra[2], ra[3], h4, l4);
        *(uint4*)(sb + soff1) = h4;           *(uint4*)(sb + 8192 + soff1) = l4;
        split8(rb[0], rb[1], h4, l4);
        *(uint4*)(sb + 16384 + soff0) = h4;   *(uint4*)(sb + 24576 + soff0) = l4;
        split8(rb[2], rb[3], h4, l4);
        *(uint4*)(sb + 16384 + soff1) = h4;   *(uint4*)(sb + 24576 + soff1) = l4;
    }
    __syncthreads();

    for (int ks = 0; ks < KS; ks++) {
        if (ks + 1 < KS) {
            int kq = (ks + 1) * 8;
            ra[0] = Ag[kq + lku * 2];     ra[1] = Ag[kq + lku * 2 + 1];
            ra[2] = Ag[kq + lku * 2 + 2]; ra[3] = Ag[kq + lku * 2 + 3];
            rb[0] = Wg[kq + lku * 2];     rb[1] = Wg[kq + lku * 2 + 1];
            rb[2] = Wg[kq + lku * 2 + 2]; rb[3] = Wg[kq + lku * 2 + 3];
        }

        const uint32_t abase = s_base + (ks & 1) * STAGE_BYTES;
        const uint32_t bbase = abase + 16384;
        #pragma unroll
        for (int k16 = 0; k16 < 2; k16++) {
            const int kb = k16 * 2;
            uint32_t Ahf[4][4], Alf[4][4], Bhf[4][2], Blf[4][2];
            // A fragments (4 m-tiles x (hi,lo)); lanes 0-15 -> rows @ unit kb,
            // lanes 16-31 -> rows @ unit kb+1
            #pragma unroll
            for (int i = 0; i < 4; i++) {
                int r  = mw + i * 16 + (lane & 15);
                int ku = kb + (lane >> 4);
                uint32_t off = r * 64 + ((ku ^ (r & 3)) << 4);
                ldsm_x4(Ahf[i], abase + off);
                ldsm_x4(Alf[i], abase + 8192 + off);
            }
            // B fragments: NON-trans ldmatrix of [n][k] rows.
            // matrix order: {n0-7,kb},{n0-7,kb+1},{n8-15,kb},{n8-15,kb+1}
            #pragma unroll
            for (int jb = 0; jb < 2; jb++) {
                int g  = lane >> 3;
                int r  = nw + jb * 16 + (g >> 1) * 8 + (lane & 7);
                int ku = kb + (g & 1);
                uint32_t off = r * 64 + ((ku ^ (r & 3)) << 4);
                uint32_t th[4], tl[4];
                ldsm_x4(th, bbase + off);
                ldsm_x4(tl, bbase + 8192 + off);
                Bhf[2*jb][0]   = th[0]; Bhf[2*jb][1]   = th[1];
                Bhf[2*jb+1][0] = th[2]; Bhf[2*jb+1][1] = th[3];
                Blf[2*jb][0]   = tl[0]; Blf[2*jb][1]   = tl[1];
                Blf[2*jb+1][0] = tl[2]; Blf[2*jb+1][1] = tl[3];
            }
            // 3-term split product: hi*hi + hi*lo + lo*hi
            #pragma unroll
            for (int i = 0; i < 4; i++)
                #pragma unroll
                for (int j = 0; j < 4; j++) {
                    mma_bf16(acc[i][j], Ahf[i], Bhf[j]);
                    mma_bf16(acc[i][j], Ahf[i], Blf[j]);
                    mma_bf16(acc[i][j], Alf[i], Bhf[j]);
                }
        }

        if (ks + 1 < KS) {
            __syncthreads();   // all warps done with the buffer we overwrite
            char* sb = smem_raw + ((ks + 1) & 1) * STAGE_BYTES;
            uint4 h4, l4;
            split8(ra[0], ra[1], h4, l4);
            *(uint4*)(sb + soff0) = h4;           *(uint4*)(sb + 8192 + soff0) = l4;
            split8(ra[2], ra[3], h4, l4);
            *(uint4*)(sb + soff1) = h4;           *(uint4*)(sb + 8192 + soff1) = l4;
            split8(rb[0], rb[1], h4, l4);
            *(uint4*)(sb + 16384 + soff0) = h4;   *(uint4*)(sb + 24576 + soff0) = l4;
            split8(rb[2], rb[3], h4, l4);
            *(uint4*)(sb + 16384 + soff1) = h4;   *(uint4*)(sb + 24576 + soff1) = l4;
            __syncthreads();
        }
    }

    // ---- epilogue: add bias, store fp32 ----
    #pragma unroll
    for (int j = 0; j < 4; j++) {
        int c = bn + nw + j * 8 + (lane & 3) * 2;
        float b0 = bih[c] + bhh[c];
        float b1 = bih[c + 1] + bhh[c + 1];
        #pragma unroll
        for (int i = 0; i < 4; i++) {
            int r0 = bm + mw + i * 16 + (lane >> 2);
            float* p0 = g_xg + (size_t)r0 * G_ + c;
            float* p1 = p0 + (size_t)8 * G_;
            *(float2*)p0 = make_float2(acc[i][j][0] + b0, acc[i][j][1] + b1);
            *(float2*)p1 = make_float2(acc[i][j][2] + b0, acc[i][j][3] + b1);
        }
    }
}

// ---------------------------------------------------------------------------
// Persistent recurrent kernel: one launch runs all T=256 steps of one layer.
// 128 CTAs x 256 threads. CTA bid owns hidden units [bid*8, bid*8+8) for all
// 4 gates; its 32x1024 w_hh slice (128 KB) stays in SMEM for the layer.
// ---------------------------------------------------------------------------
#define RBLK 128
#define REC_SMEM_FLOATS (32*1024 + 512 + 2048 + 512)

__global__ __launch_bounds__(256, 1) void lstm_rec_kernel(
    const float* __restrict__ whh, int osel)
{
    extern __shared__ __align__(16) float smem[];
    float* sW = smem;               // [32][1024]  w_hh slice (row = gate*8 + unit)
    float* sC = sW + 32*1024;       // [512]  c state, cell = unit*64 + batch
    float* sG = sC + 512;           // [32][64] gate pre-activations
    float* sH = sG + 2048;          // [512]  h staging for hseq transpose-store

    const int tid = threadIdx.x;
    const int bid = blockIdx.x;
    const int u0  = bid * 8;
    const int b   = tid & 63;
    const int rg  = tid >> 6;
    float* hseq = (osel == 1) ? g_hseqA : g_hseqB;

    #pragma unroll
    for (int i = 0; i < 32; i++) {
        int f  = tid + i * 256;
        int r  = f >> 8;
        int kq = f & 255;
        int q = r >> 3, j = r & 7;
        ((float4*)sW)[r * 256 + kq] =
            *(const float4*)(whh + (size_t)(q * H_ + u0 + j) * H_ + kq * 4);
    }
    sC[tid] = 0.f; sC[tid + 256] = 0.f;
    g_hbuf[0][u0 * 64 + tid] = 0.f;
    g_hbuf[0][u0 * 64 + tid + 256] = 0.f;
    __syncthreads();
    grid_barrier(gridDim.x);

    int par = 0;
    const float* wr = sW + (rg * 8) * 1024;
    for (int t = 0; t < T_; t++) {
        const float4* xr = (const float4*)(g_xg + (size_t)(t * 64 + b) * G_ + rg * H_ + u0);
        float4 x0 = xr[0], x1 = xr[1];
        u64 acc[8];
        acc[0] = pack2(x0.x, 0.f); acc[1] = pack2(x0.y, 0.f);
        acc[2] = pack2(x0.z, 0.f); acc[3] = pack2(x0.w, 0.f);
        acc[4] = pack2(x1.x, 0.f); acc[5] = pack2(x1.y, 0.f);
        acc[6] = pack2(x1.z, 0.f); acc[7] = pack2(x1.w, 0.f);

        const float* hb = g_hbuf[par] + b;
        #pragma unroll 1
        for (int k = 0; k < H_; k += 8) {
            // front-batched loads: MLP 8 to cover L2 latency
            float h0 = __ldcg(hb + (k + 0) * 64);
            float h1 = __ldcg(hb + (k + 1) * 64);
            float h2 = __ldcg(hb + (k + 2) * 64);
            float h3 = __ldcg(hb + (k + 3) * 64);
            float h4 = __ldcg(hb + (k + 4) * 64);
            float h5 = __ldcg(hb + (k + 5) * 64);
            float h6 = __ldcg(hb + (k + 6) * 64);
            float h7 = __ldcg(hb + (k + 7) * 64);
            u64 hp0 = pack2(h0, h1);
            u64 hp1 = pack2(h2, h3);
            u64 hp2 = pack2(h4, h5);
            u64 hp3 = pack2(h6, h7);
            #pragma unroll
            for (int j = 0; j < 8; j++) {
                const float* w = wr + j * 1024 + k;
                ulonglong2 w01 = *(const ulonglong2*)w;
                ulonglong2 w23 = *(const ulonglong2*)(w + 4);
                ffma2(acc[j], hp0, w01.x);
                ffma2(acc[j], hp1, w01.y);
                ffma2(acc[j], hp2, w23.x);
                ffma2(acc[j], hp3, w23.y);
            }
        }
        #pragma unroll
        for (int j = 0; j < 8; j++) {
            float lo, hi; unpack2(acc[j], lo, hi);
            sG[(rg * 8 + j) * 64 + b] = lo + hi;
        }
        __syncthreads();

        #pragma unroll
        for (int rep = 0; rep < 2; rep++) {
            int cell = tid + rep * 256;
            int j = cell >> 6, bb = cell & 63;
            float vi = sG[(0 * 8 + j) * 64 + bb];
            float vf = sG[(1 * 8 + j) * 64 + bb];
            float vg = sG[(2 * 8 + j) * 64 + bb];
            float vo = sG[(3 * 8 + j) * 64 + bb];
            float c = sigmf(vf) * sC[cell] + sigmf(vi) * tanhf(vg);
            sC[cell] = c;
            float hv = sigmf(vo) * tanhf(c);
            g_hbuf[par ^ 1][u0 * 64 + cell] = hv;
            sH[cell] = hv;
        }
        __syncthreads();

        #pragma unroll
        for (int rep = 0; rep < 2; rep++) {
            int idx = tid + rep * 256;
            int j2 = idx & 7, b3 = idx >> 3;
            hseq[(size_t)(t * 64 + b3) * H_ + u0 + j2] = sH[j2 * 64 + b3];
        }
        grid_barrier(gridDim.x);
        par ^= 1;
    }
}

// ---------------------------------------------------------------------------
// Final FC: out[b] = dot(h_T[b,:], fc_w) + fc_b
// ---------------------------------------------------------------------------
__global__ void fc_kernel(const float* __restrict__ fcw, const float* __restrict__ fcb,
                          float* __restrict__ out)
{
    int bb = blockIdx.x, tid = threadIdx.x;
    const float* h = g_hseqA + (size_t)(255 * 64 + bb) * H_;
    float s = 0.f;
    for (int k = tid * 4; k < H_; k += 128 * 4) {
        float4 hv = *(const float4*)(h + k);
        float4 wv = *(const float4*)(fcw + k);
        s += hv.x * wv.x + hv.y * wv.y + hv.z * wv.z + hv.w * wv.w;
    }
    #pragma unroll
    for (int o = 16; o; o >>= 1) s += __shfl_xor_sync(0xffffffffu, s, o);
    __shared__ float ws[4];
    if ((tid & 31) == 0) ws[tid >> 5] = s;
    __syncthreads();
    if (tid == 0) out[bb] = ws[0] + ws[1] + ws[2] + ws[3] + fcb[0];
}

// ---------------------------------------------------------------------------
// Launch
// ---------------------------------------------------------------------------
extern "C" void kernel_launch(void* const* d_in, const int* in_sizes, int n_in,
                              void* d_out, int out_size)
{
    const float* x     = (const float*)d_in[0];
    const float* w_ih0 = (const float*)d_in[1];
    const float* w_hh0 = (const float*)d_in[2];
    const float* b_ih0 = (const float*)d_in[3];
    const float* b_hh0 = (const float*)d_in[4];
    const float* w_ih1 = (const float*)d_in[5];
    const float* w_hh1 = (const float*)d_in[6];
    const float* b_ih1 = (const float*)d_in[7];
    const float* b_hh1 = (const float*)d_in[8];
    const float* w_ih2 = (const float*)d_in[9];
    const float* w_hh2 = (const float*)d_in[10];
    const float* b_ih2 = (const float*)d_in[11];
    const float* b_hh2 = (const float*)d_in[12];
    const float* fc_w  = (const float*)d_in[13];
    const float* fc_b  = (const float*)d_in[14];
    float* out = (float*)d_out;

    size_t rec_smem  = (size_t)REC_SMEM_FLOATS * sizeof(float);   // 143,360 B
    size_t gemm_smem = 2 * STAGE_BYTES;                           // 65,536 B
    cudaFuncSetAttribute(lstm_rec_kernel,
                         cudaFuncAttributeMaxDynamicSharedMemorySize, (int)rec_smem);
    cudaFuncSetAttribute(gemm_mma_kernel,
                         cudaFuncAttributeMaxDynamicSharedMemorySize, (int)gemm_smem);

    dim3 ggrid(G_ / 128, M_ / 128);   // (32, 128)

    // layer 0: input is x (remapped rows), K=256
    gemm_mma_kernel<<<ggrid, 256, gemm_smem>>>(x, 0, w_ih0, b_ih0, b_hh0, 256, 1);
    lstm_rec_kernel<<<RBLK, 256, rec_smem>>>(w_hh0, 1);   // -> hseqA
    // layer 1: input hseqA, K=1024
    gemm_mma_kernel<<<ggrid, 256, gemm_smem>>>(nullptr, 1, w_ih1, b_ih1, b_hh1, H_, 0);
    lstm_rec_kernel<<<RBLK, 256, rec_smem>>>(w_hh1, 2);   // -> hseqB
    // layer 2: input hseqB, K=1024
    gemm_mma_kernel<<<ggrid, 256, gemm_smem>>>(nullptr, 2, w_ih2, b_ih2, b_hh2, H_, 0);
    lstm_rec_kernel<<<RBLK, 256, rec_smem>>>(w_hh2, 1);   // -> hseqA
    // final FC
    fc_kernel<<<B_, 128>>>(fc_w, fc_b, out);
}

// round 11
// speedup vs baseline: 1.4441x; 1.3781x over previous
#include <cuda_runtime.h>
#include <cuda_bf16.h>
#include <cstdint>

// ---------------------------------------------------------------------------
// Problem constants
// ---------------------------------------------------------------------------
#define H_  1024
#define G_  4096      // 4*H
#define B_  64
#define T_  256
#define M_  16384     // B*T

// ---------------------------------------------------------------------------
// Scratch (device globals — no allocation allowed)
// ---------------------------------------------------------------------------
__device__ float g_xg[(size_t)M_ * G_];        // 256 MB: per-layer input projections
__device__ float g_hseqA[(size_t)M_ * H_];     // 64 MB : layer output sequence (t-major rows)
__device__ float g_hseqB[(size_t)M_ * H_];     // 64 MB : ping-pong
// h state, PAIR-INTERLEAVED layout: h[k][b] stored at (k>>1)*128 + b*2 + (k&1)
// so that (h[k],h[k+1]) for one batch is a contiguous 8-byte f32x2 operand.
__device__ float g_hbuf[2][H_ * B_];
__device__ unsigned g_bar_count;
__device__ volatile unsigned g_bar_gen;

typedef unsigned long long u64;

// ---------------------------------------------------------------------------
// Packed f32x2 helpers (recurrent kernel)
// ---------------------------------------------------------------------------
__device__ __forceinline__ u64 pack2(float x, float y) {
    u64 r; asm("mov.b64 %0, {%1, %2};" : "=l"(r) : "f"(x), "f"(y)); return r;
}
__device__ __forceinline__ void unpack2(u64 v, float& x, float& y) {
    asm("mov.b64 {%0, %1}, %2;" : "=f"(x), "=f"(y) : "l"(v));
}
__device__ __forceinline__ void ffma2(u64& acc, u64 a, u64 b) {
    asm("fma.rn.f32x2 %0, %1, %2, %3;" : "=l"(acc) : "l"(a), "l"(b), "l"(acc));
}
__device__ __forceinline__ float sigmf(float x) { return 1.0f / (1.0f + expf(-x)); }

// cp.async 16B (global -> shared)
__device__ __forceinline__ void cpasync16(uint32_t dst, const float* src) {
    asm volatile("cp.async.cg.shared.global [%0], [%1], 16;" :: "r"(dst), "l"(src));
}
#define CP_COMMIT() asm volatile("cp.async.commit_group;")
#define CP_WAIT0()  asm volatile("cp.async.wait_group 0;")

// ---------------------------------------------------------------------------
// Grid barrier (sense-reversing; 128 co-resident CTAs)
// ---------------------------------------------------------------------------
__device__ __forceinline__ void grid_barrier(unsigned nblocks) {
    __syncthreads();
    if (threadIdx.x == 0) {
        unsigned gen = g_bar_gen;
        __threadfence();
        unsigned t = atomicAdd(&g_bar_count, 1u);
        if (t == nblocks - 1u) {
            g_bar_count = 0u;
            __threadfence();
            g_bar_gen = gen + 1u;
        } else {
            while (g_bar_gen == gen) { }
        }
        __threadfence();
    }
    __syncthreads();
}

// ---------------------------------------------------------------------------
// bf16 split helpers (GEMM): x = hi(x) + lo(x), each bf16 (8-bit mantissa)
// ---------------------------------------------------------------------------
__device__ __forceinline__ void split8(const float4 a, const float4 b,
                                       uint4& h, uint4& l)
{
    float v[8] = {a.x, a.y, a.z, a.w, b.x, b.y, b.z, b.w};
    unsigned short hs[8], ls[8];
    #pragma unroll
    for (int q = 0; q < 8; q++) {
        __nv_bfloat16 bh = __float2bfloat16(v[q]);
        hs[q] = __bfloat16_as_ushort(bh);
        float res = v[q] - __bfloat162float(bh);
        ls[q] = __bfloat16_as_ushort(__float2bfloat16(res));
    }
    h.x = (uint32_t)hs[0] | ((uint32_t)hs[1] << 16);
    h.y = (uint32_t)hs[2] | ((uint32_t)hs[3] << 16);
    h.z = (uint32_t)hs[4] | ((uint32_t)hs[5] << 16);
    h.w = (uint32_t)hs[6] | ((uint32_t)hs[7] << 16);
    l.x = (uint32_t)ls[0] | ((uint32_t)ls[1] << 16);
    l.y = (uint32_t)ls[2] | ((uint32_t)ls[3] << 16);
    l.z = (uint32_t)ls[4] | ((uint32_t)ls[5] << 16);
    l.w = (uint32_t)ls[6] | ((uint32_t)ls[7] << 16);
}

__device__ __forceinline__ void ldsm_x4(uint32_t* r, uint32_t addr) {
    asm volatile("ldmatrix.sync.aligned.m8n8.x4.shared.b16 {%0,%1,%2,%3}, [%4];"
        : "=r"(r[0]), "=r"(r[1]), "=r"(r[2]), "=r"(r[3]) : "r"(addr));
}
__device__ __forceinline__ void mma_bf16(float* c, const uint32_t* a, const uint32_t* b) {
    asm volatile(
        "mma.sync.aligned.m16n8k16.row.col.f32.bf16.bf16.f32 "
        "{%0,%1,%2,%3},{%4,%5,%6,%7},{%8,%9},{%0,%1,%2,%3};"
        : "+f"(c[0]), "+f"(c[1]), "+f"(c[2]), "+f"(c[3])
        : "r"(a[0]), "r"(a[1]), "r"(a[2]), "r"(a[3]), "r"(b[0]), "r"(b[1]));
}

// ---------------------------------------------------------------------------
// Tensor-core input-projection GEMM (bf16x3 split, rel err ~1e-6):
//   xg[m, n] = sum_k A[m,k] * W[n,k] + bih[n] + bhh[n]
// Unchanged from R10 (passing).
// ---------------------------------------------------------------------------
#define STAGE_BYTES 32768    // Ah(8K) Al(8K) Bh(8K) Bl(8K)

__global__ __launch_bounds__(256, 1) void gemm_mma_kernel(
    const float* __restrict__ Aext, int insel,
    const float* __restrict__ W,
    const float* __restrict__ bih, const float* __restrict__ bhh,
    int K, int remap)
{
    extern __shared__ __align__(16) char smem_raw[];
    const float* A = Aext ? Aext : (insel == 1 ? g_hseqA : g_hseqB);

    const int tid  = threadIdx.x;
    const int lane = tid & 31;
    const int wid  = tid >> 5;
    const int bn = blockIdx.x * 128;
    const int bm = blockIdx.y * 128;
    const int mw = (wid & 1) * 64;     // warp m offset in block
    const int nw = (wid >> 1) * 32;    // warp n offset in block

    const int lr  = tid >> 1;          // 0..127
    const int lku = (tid & 1) * 2;     // 0 or 2
    int arow = bm + lr;
    if (remap) arow = (arow & 63) * 256 + (arow >> 6);
    const float4* Ag = (const float4*)(A + (size_t)arow * K);
    const float4* Wg = (const float4*)(W + (size_t)(bn + lr) * K);

    const uint32_t s_base = (uint32_t)__cvta_generic_to_shared(smem_raw);
    const int ph0 = (lku ^ (lr & 3));
    const int ph1 = ((lku + 1) ^ (lr & 3));
    const int soff0 = lr * 64 + ph0 * 16;
    const int soff1 = lr * 64 + ph1 * 16;

    float acc[4][4][4];
    #pragma unroll
    for (int i = 0; i < 4; i++)
        #pragma unroll
        for (int j = 0; j < 4; j++)
            #pragma unroll
            for (int q = 0; q < 4; q++) acc[i][j][q] = 0.f;

    float4 ra[4], rb[4];
    const int KS = K / 32;

    {
        ra[0] = Ag[lku * 2];     ra[1] = Ag[lku * 2 + 1];
        ra[2] = Ag[lku * 2 + 2]; ra[3] = Ag[lku * 2 + 3];
        rb[0] = Wg[lku * 2];     rb[1] = Wg[lku * 2 + 1];
        rb[2] = Wg[lku * 2 + 2]; rb[3] = Wg[lku * 2 + 3];
        uint4 h4, l4;
        char* sb = smem_raw;
        split8(ra[0], ra[1], h4, l4);
        *(uint4*)(sb + soff0) = h4;           *(uint4*)(sb + 8192 + soff0) = l4;
        split8(ra[2], ra[3], h4, l4);
        *(uint4*)(sb + soff1) = h4;           *(uint4*)(sb + 8192 + soff1) = l4;
        split8(rb[0], rb[1], h4, l4);
        *(uint4*)(sb + 16384 + soff0) = h4;   *(uint4*)(sb + 24576 + soff0) = l4;
        split8(rb[2], rb[3], h4, l4);
        *(uint4*)(sb + 16384 + soff1) = h4;   *(uint4*)(sb + 24576 + soff1) = l4;
    }
    __syncthreads();

    for (int ks = 0; ks < KS; ks++) {
        if (ks + 1 < KS) {
            int kq = (ks + 1) * 8;
            ra[0] = Ag[kq + lku * 2];     ra[1] = Ag[kq + lku * 2 + 1];
            ra[2] = Ag[kq + lku * 2 + 2]; ra[3] = Ag[kq + lku * 2 + 3];
            rb[0] = Wg[kq + lku * 2];     rb[1] = Wg[kq + lku * 2 + 1];
            rb[2] = Wg[kq + lku * 2 + 2]; rb[3] = Wg[kq + lku * 2 + 3];
        }

        const uint32_t abase = s_base + (ks & 1) * STAGE_BYTES;
        const uint32_t bbase = abase + 16384;
        #pragma unroll
        for (int k16 = 0; k16 < 2; k16++) {
            const int kb = k16 * 2;
            uint32_t Ahf[4][4], Alf[4][4], Bhf[4][2], Blf[4][2];
            #pragma unroll
            for (int i = 0; i < 4; i++) {
                int r  = mw + i * 16 + (lane & 15);
                int ku = kb + (lane >> 4);
                uint32_t off = r * 64 + ((ku ^ (r & 3)) << 4);
                ldsm_x4(Ahf[i], abase + off);
                ldsm_x4(Alf[i], abase + 8192 + off);
            }
            #pragma unroll
            for (int jb = 0; jb < 2; jb++) {
                int g  = lane >> 3;
                int r  = nw + jb * 16 + (g >> 1) * 8 + (lane & 7);
                int ku = kb + (g & 1);
                uint32_t off = r * 64 + ((ku ^ (r & 3)) << 4);
                uint32_t th[4], tl[4];
                ldsm_x4(th, bbase + off);
                ldsm_x4(tl, bbase + 8192 + off);
                Bhf[2*jb][0]   = th[0]; Bhf[2*jb][1]   = th[1];
                Bhf[2*jb+1][0] = th[2]; Bhf[2*jb+1][1] = th[3];
                Blf[2*jb][0]   = tl[0]; Blf[2*jb][1]   = tl[1];
                Blf[2*jb+1][0] = tl[2]; Blf[2*jb+1][1] = tl[3];
            }
            #pragma unroll
            for (int i = 0; i < 4; i++)
                #pragma unroll
                for (int j = 0; j < 4; j++) {
                    mma_bf16(acc[i][j], Ahf[i], Bhf[j]);
                    mma_bf16(acc[i][j], Ahf[i], Blf[j]);
                    mma_bf16(acc[i][j], Alf[i], Bhf[j]);
                }
        }

        if (ks + 1 < KS) {
            __syncthreads();
            char* sb = smem_raw + ((ks + 1) & 1) * STAGE_BYTES;
            uint4 h4, l4;
            split8(ra[0], ra[1], h4, l4);
            *(uint4*)(sb + soff0) = h4;           *(uint4*)(sb + 8192 + soff0) = l4;
            split8(ra[2], ra[3], h4, l4);
            *(uint4*)(sb + soff1) = h4;           *(uint4*)(sb + 8192 + soff1) = l4;
            split8(rb[0], rb[1], h4, l4);
            *(uint4*)(sb + 16384 + soff0) = h4;   *(uint4*)(sb + 24576 + soff0) = l4;
            split8(rb[2], rb[3], h4, l4);
            *(uint4*)(sb + 16384 + soff1) = h4;   *(uint4*)(sb + 24576 + soff1) = l4;
            __syncthreads();
        }
    }

    #pragma unroll
    for (int j = 0; j < 4; j++) {
        int c = bn + nw + j * 8 + (lane & 3) * 2;
        float b0 = bih[c] + bhh[c];
        float b1 = bih[c + 1] + bhh[c + 1];
        #pragma unroll
        for (int i = 0; i < 4; i++) {
            int r0 = bm + mw + i * 16 + (lane >> 2);
            float* p0 = g_xg + (size_t)r0 * G_ + c;
            float* p1 = p0 + (size_t)8 * G_;
            *(float2*)p0 = make_float2(acc[i][j][0] + b0, acc[i][j][1] + b1);
            *(float2*)p1 = make_float2(acc[i][j][2] + b0, acc[i][j][3] + b1);
        }
    }
}

// ---------------------------------------------------------------------------
// Persistent recurrent kernel (R10 + SMEM-staged h):
// 128 CTAs x 256 threads; CTA owns 8 hidden units x 4 gates; 128KB w_hh slice
// resident in SMEM. NEW: h is cp.async-staged into SMEM in 8 double-buffered
// 32KB chunks per step (pair-interleaved layout -> LDS.64 gives a packed
// f32x2 operand directly), removing the per-iteration L2 latency exposure.
// SMEM: 128K (W) + 64K (h x2) + 12.25K (C,G,Hstage) = 204.0 KB
// ---------------------------------------------------------------------------
#define RBLK 128
#define CHUNK_K    128                  // k-values per chunk
#define CHUNK_FLT  (CHUNK_K * B_)      // 8192 floats = 32KB
#define N_CHUNK    (H_ / CHUNK_K)      // 8
#define REC_SMEM_FLOATS (32*1024 + 2*CHUNK_FLT + 512 + 2048 + 512)

__global__ __launch_bounds__(256, 1) void lstm_rec_kernel(
    const float* __restrict__ whh, int osel)
{
    extern __shared__ __align__(16) float smem[];
    float* sW  = smem;                  // [32][1024]  w_hh slice (row = gate*8 + unit)
    float* sHb = sW + 32*1024;          // [2][8192]   h chunk double buffer
    float* sC  = sHb + 2*CHUNK_FLT;     // [512]  c state
    float* sG  = sC + 512;              // [32][64] gate pre-activations
    float* sH  = sG + 2048;             // [512]  h staging for hseq store

    const int tid = threadIdx.x;
    const int bid = blockIdx.x;
    const int u0  = bid * 8;
    const int b   = tid & 63;
    const int b2  = b * 2;
    const int rg  = tid >> 6;
    float* hseq = (osel == 1) ? g_hseqA : g_hseqB;
    const uint32_t sHb_addr = (uint32_t)__cvta_generic_to_shared(sHb);

    // Load w_hh slice: rows q*H + u0 + j  ->  sW row q*8+j
    #pragma unroll
    for (int i = 0; i < 32; i++) {
        int f  = tid + i * 256;
        int r  = f >> 8;
        int kq = f & 255;
        int q = r >> 3, j = r & 7;
        ((float4*)sW)[r * 256 + kq] =
            *(const float4*)(whh + (size_t)(q * H_ + u0 + j) * H_ + kq * 4);
    }
    sC[tid] = 0.f; sC[tid + 256] = 0.f;
    g_hbuf[0][u0 * 64 + tid] = 0.f;          // covers this CTA's (u,b) slice
    g_hbuf[0][u0 * 64 + tid + 256] = 0.f;    // (pair-interleaved, same range)
    __syncthreads();
    grid_barrier(gridDim.x);

    int par = 0;
    const float* wr = sW + (rg * 8) * 1024;
    for (int t = 0; t < T_; t++) {
        // issue chunk 0 copy of this step's h
        {
            const float* src = g_hbuf[par];
            #pragma unroll
            for (int i = 0; i < 8; i++) {
                int f = tid + i * 256;               // float4 index
                cpasync16(sHb_addr + (uint32_t)f * 16u, src + f * 4);
            }
            CP_COMMIT();
        }

        // init accumulators from xg (row m = t*64+b, cols rg*H + u0 .. +7)
        const float4* xr = (const float4*)(g_xg + (size_t)(t * 64 + b) * G_ + rg * H_ + u0);
        float4 x0 = xr[0], x1 = xr[1];
        u64 acc[8];
        acc[0] = pack2(x0.x, 0.f); acc[1] = pack2(x0.y, 0.f);
        acc[2] = pack2(x0.z, 0.f); acc[3] = pack2(x0.w, 0.f);
        acc[4] = pack2(x1.x, 0.f); acc[5] = pack2(x1.y, 0.f);
        acc[6] = pack2(x1.z, 0.f); acc[7] = pack2(x1.w, 0.f);

        for (int c = 0; c < N_CHUNK; c++) {
            CP_WAIT0();          // this thread's copy of chunk c done
            __syncthreads();     // all threads' copies done; all done with buf c-1
            if (c + 1 < N_CHUNK) {
                const float* src = g_hbuf[par] + (c + 1) * CHUNK_FLT;
                uint32_t dst = sHb_addr + (uint32_t)(((c + 1) & 1) * CHUNK_FLT) * 4u;
                #pragma unroll
                for (int i = 0; i < 8; i++) {
                    int f = tid + i * 256;
                    cpasync16(dst + (uint32_t)f * 16u, src + f * 4);
                }
                CP_COMMIT();
            }

            const float* hc = sHb + (c & 1) * CHUNK_FLT;
            const int kbase = c * CHUNK_K;
            #pragma unroll 4
            for (int kk = 0; kk < CHUNK_K; kk += 8) {
                const int p = kk >> 1;               // pair index in chunk
                u64 hp0 = *(const u64*)&hc[(p + 0) * 128 + b2];
                u64 hp1 = *(const u64*)&hc[(p + 1) * 128 + b2];
                u64 hp2 = *(const u64*)&hc[(p + 2) * 128 + b2];
                u64 hp3 = *(const u64*)&hc[(p + 3) * 128 + b2];
                const int k = kbase + kk;
                #pragma unroll
                for (int j = 0; j < 8; j++) {
                    const float* w = wr + j * 1024 + k;
                    ulonglong2 w01 = *(const ulonglong2*)w;
                    ulonglong2 w23 = *(const ulonglong2*)(w + 4);
                    ffma2(acc[j], hp0, w01.x);
                    ffma2(acc[j], hp1, w01.y);
                    ffma2(acc[j], hp2, w23.x);
                    ffma2(acc[j], hp3, w23.y);
                }
            }
        }

        #pragma unroll
        for (int j = 0; j < 8; j++) {
            float lo, hi; unpack2(acc[j], lo, hi);
            sG[(rg * 8 + j) * 64 + b] = lo + hi;
        }
        __syncthreads();

        // pointwise LSTM cell update: 512 cells over 256 threads
        #pragma unroll
        for (int rep = 0; rep < 2; rep++) {
            int cell = tid + rep * 256;
            int j = cell >> 6, bb = cell & 63;
            float vi = sG[(0 * 8 + j) * 64 + bb];
            float vf = sG[(1 * 8 + j) * 64 + bb];
            float vg = sG[(2 * 8 + j) * 64 + bb];
            float vo = sG[(3 * 8 + j) * 64 + bb];
            float cval = sigmf(vf) * sC[cell] + sigmf(vi) * tanhf(vg);
            sC[cell] = cval;
            float hv = sigmf(vo) * tanhf(cval);
            int u = u0 + j;
            // pair-interleaved h layout: (k>>1)*128 + b*2 + (k&1)
            g_hbuf[par ^ 1][(u >> 1) * 128 + bb * 2 + (u & 1)] = hv;
            sH[cell] = hv;
        }
        __syncthreads();

        // hseq store: row m = t*64+b, cols u0..u0+7
        #pragma unroll
        for (int rep = 0; rep < 2; rep++) {
            int idx = tid + rep * 256;
            int j2 = idx & 7, b3 = idx >> 3;
            hseq[(size_t)(t * 64 + b3) * H_ + u0 + j2] = sH[j2 * 64 + b3];
        }
        grid_barrier(gridDim.x);
        par ^= 1;
    }
}

// ---------------------------------------------------------------------------
// Final FC: out[b] = dot(h_T[b,:], fc_w) + fc_b
// ---------------------------------------------------------------------------
__global__ void fc_kernel(const float* __restrict__ fcw, const float* __restrict__ fcb,
                          float* __restrict__ out)
{
    int bb = blockIdx.x, tid = threadIdx.x;
    const float* h = g_hseqA + (size_t)(255 * 64 + bb) * H_;
    float s = 0.f;
    for (int k = tid * 4; k < H_; k += 128 * 4) {
        float4 hv = *(const float4*)(h + k);
        float4 wv = *(const float4*)(fcw + k);
        s += hv.x * wv.x + hv.y * wv.y + hv.z * wv.z + hv.w * wv.w;
    }
    #pragma unroll
    for (int o = 16; o; o >>= 1) s += __shfl_xor_sync(0xffffffffu, s, o);
    __shared__ float ws[4];
    if ((tid & 31) == 0) ws[tid >> 5] = s;
    __syncthreads();
    if (tid == 0) out[bb] = ws[0] + ws[1] + ws[2] + ws[3] + fcb[0];
}

// ---------------------------------------------------------------------------
// Launch
// ---------------------------------------------------------------------------
extern "C" void kernel_launch(void* const* d_in, const int* in_sizes, int n_in,
                              void* d_out, int out_size)
{
    const float* x     = (const float*)d_in[0];
    const float* w_ih0 = (const float*)d_in[1];
    const float* w_hh0 = (const float*)d_in[2];
    const float* b_ih0 = (const float*)d_in[3];
    const float* b_hh0 = (const float*)d_in[4];
    const float* w_ih1 = (const float*)d_in[5];
    const float* w_hh1 = (const float*)d_in[6];
    const float* b_ih1 = (const float*)d_in[7];
    const float* b_hh1 = (const float*)d_in[8];
    const float* w_ih2 = (const float*)d_in[9];
    const float* w_hh2 = (const float*)d_in[10];
    const float* b_ih2 = (const float*)d_in[11];
    const float* b_hh2 = (const float*)d_in[12];
    const float* fc_w  = (const float*)d_in[13];
    const float* fc_b  = (const float*)d_in[14];
    float* out = (float*)d_out;

    size_t rec_smem  = (size_t)REC_SMEM_FLOATS * sizeof(float);   // 208,896 B
    size_t gemm_smem = 2 * STAGE_BYTES;                           // 65,536 B
    cudaFuncSetAttribute(lstm_rec_kernel,
                         cudaFuncAttributeMaxDynamicSharedMemorySize, (int)rec_smem);
    cudaFuncSetAttribute(gemm_mma_kernel,
                         cudaFuncAttributeMaxDynamicSharedMemorySize, (int)gemm_smem);

    dim3 ggrid(G_ / 128, M_ / 128);   // (32, 128)

    // layer 0: input is x (remapped rows), K=256
    gemm_mma_kernel<<<ggrid, 256, gemm_smem>>>(x, 0, w_ih0, b_ih0, b_hh0, 256, 1);
    lstm_rec_kernel<<<RBLK, 256, rec_smem>>>(w_hh0, 1);   // -> hseqA
    // layer 1: input hseqA, K=1024
    gemm_mma_kernel<<<ggrid, 256, gemm_smem>>>(nullptr, 1, w_ih1, b_ih1, b_hh1, H_, 0);
    lstm_rec_kernel<<<RBLK, 256, rec_smem>>>(w_hh1, 2);   // -> hseqB
    // layer 2: input hseqB, K=1024
    gemm_mma_kernel<<<ggrid, 256, gemm_smem>>>(nullptr, 2, w_ih2, b_ih2, b_hh2, H_, 0);
    lstm_rec_kernel<<<RBLK, 256, rec_smem>>>(w_hh2, 1);   // -> hseqA
    // final FC
    fc_kernel<<<B_, 128>>>(fc_w, fc_b, out);
}